// round 16
// baseline (speedup 1.0000x reference)
#include <cuda_runtime.h>
#include <cstdint>

// Shapes (fixed): n=1024 tokens, 2L=512, H=512, H2=256.
#define NTOK 1024
#define KIN  512
#define HH   512
#define H2D  256
#define NQUAD 64                          // H2/4 quad-merged terms
#define SCALE_2LOG2E 2.885390081777927f   // 2*log2(e)
#define ONE2 0x3F8000003F800000ULL        // (1.0f, 1.0f) packed

// Scratch (device globals; no allocations allowed)
__device__ float g_ah[NTOK * HH];
__device__ float g_am[NTOK * HH];
__device__ float g_Ep1[NTOK * NQUAD];  // head side, quad member 0 (h = 4q)
__device__ float g_Ep2[NTOK * NQUAD];  // member 1 (h = 4q+1)
__device__ float g_Ep3[NTOK * NQUAD];  // member 2
__device__ float g_Ep4[NTOK * NQUAD];  // member 3
__device__ float g_Eq1[NTOK * NQUAD];  // mod side (bias folded), member 0
__device__ float g_Eq2[NTOK * NQUAD];
__device__ float g_Eq3[NTOK * NQUAD];
__device__ float g_Eq4[NTOK * NQUAD];
__device__ float g_w1[NQUAD];          // -2*w[4q+0]
__device__ float g_w2[NQUAD];          // -2*w[4q+1]
__device__ float g_w3[NQUAD];          // -2*w[4q+2]
__device__ float g_w4[NQUAD];          // -2*w[4q+3]
__device__ float g_C;                  // sum(w) + outBias

// ---------------- packed f32x2 helpers (sm_103a FFMA2 path) ----------------
__device__ __forceinline__ uint64_t fma2(uint64_t a, uint64_t b, uint64_t c) {
    uint64_t d;
    asm("fma.rn.f32x2 %0, %1, %2, %3;" : "=l"(d) : "l"(a), "l"(b), "l"(c));
    return d;
}
__device__ __forceinline__ uint64_t mul2(uint64_t a, uint64_t b) {
    uint64_t d;
    asm("mul.rn.f32x2 %0, %1, %2;" : "=l"(d) : "l"(a), "l"(b));
    return d;
}
__device__ __forceinline__ uint64_t pack2(float lo, float hi) {
    uint64_t d;
    asm("mov.b64 %0, {%1, %2};" : "=l"(d) : "f"(lo), "f"(hi));
    return d;
}
__device__ __forceinline__ void unpack2(uint64_t p, float& lo, float& hi) {
    asm("mov.b64 {%0, %1}, %2;" : "=f"(lo), "=f"(hi) : "l"(p));
}
__device__ __forceinline__ uint64_t splat2(float v) {
    uint64_t d;
    asm("mov.b64 %0, {%1, %1};" : "=l"(d) : "f"(v));
    return d;
}
__device__ __forceinline__ float rcpf(float x) {
    float r;
    asm("rcp.approx.f32 %0, %1;" : "=f"(r) : "f"(x));
    return r;
}
__device__ __forceinline__ float fast_tanh(float x) {   // 1 - 2/(exp(2x)+1)
    float e;
    asm("ex2.approx.f32 %0, %1;" : "=f"(e) : "f"(x * SCALE_2LOG2E));
    return 1.0f - 2.0f * rcpf(e + 1.0f);
}
__device__ __forceinline__ float fast_ex2(float x) {
    float e;
    asm("ex2.approx.f32 %0, %1;" : "=f"(e) : "f"(x));
    return e;
}

// ---------------------------------------------------------------------------
// Kernel 1: [ah | am] = tanh( x @ [W_foh | W_fom] + catBias )
// 64x64 tile, BK=16, 256 threads, 4x4 micro (acc packed f32x2 along j),
// double-buffered smem. Grid (16,16) = 256 blocks.
// ---------------------------------------------------------------------------
__global__ __launch_bounds__(256)
void gemm1_tanh(const float* __restrict__ l0, const float* __restrict__ l1,
                const float* __restrict__ Wfoh, const float* __restrict__ Wfom,
                const float* __restrict__ catBias) {
    __shared__ __align__(16) float As[2][16][68];   // As[buf][k][m]
    __shared__ __align__(16) float Bs[2][16][68];   // Bs[buf][k][n]

    const int tid = threadIdx.x;
    const int n0 = blockIdx.x * 64;        // combined N (0..1023)
    const int m0 = blockIdx.y * 64;

    const bool head = (n0 < 512);
    const float* __restrict__ W = head ? Wfoh : Wfom;
    const int   wcol = head ? n0 : (n0 - 512);
    float* __restrict__ out = head ? g_ah : g_am;

    const int tx = tid & 15;
    const int ty = tid >> 4;
    const int lm  = tid >> 2;              // 0..63 (A rows)
    const int lk4 = (tid & 3) * 4;         // 0,4,8,12
    const int lk  = tid >> 4;              // 0..15 (B k)
    const int ln  = (tid & 15) * 4;        // 0..60 (B n)

    float4 av = *(const float4*)(l0 + (size_t)(m0 + lm) * 256 + lk4);
    float4 bv = *(const float4*)(W + (size_t)lk * HH + wcol + ln);
    As[0][lk4 + 0][lm] = av.x;
    As[0][lk4 + 1][lm] = av.y;
    As[0][lk4 + 2][lm] = av.z;
    As[0][lk4 + 3][lm] = av.w;
    *(float4*)&Bs[0][lk][ln] = bv;
    __syncthreads();

    uint64_t accP[4][2] = {};              // [i][j-pair], f32x2
    int cur = 0;

    for (int k0 = 0; k0 < KIN; k0 += 16) {
        float4 av2, bv2;
        const int kn = k0 + 16;
        if (kn < KIN) {
            const float* __restrict__ xsrc =
                (kn < 256) ? (l0 + (size_t)(m0 + lm) * 256 + (kn + lk4))
                           : (l1 + (size_t)(m0 + lm) * 256 + (kn - 256 + lk4));
            av2 = *(const float4*)xsrc;
            bv2 = *(const float4*)(W + (size_t)(kn + lk) * HH + wcol + ln);
        }

#pragma unroll
        for (int kk = 0; kk < 16; kk++) {
            float4 a4 = *(const float4*)&As[cur][kk][ty * 4];
            ulonglong2 b2 = *(const ulonglong2*)&Bs[cur][kk][tx * 4];
            float aa[4] = {a4.x, a4.y, a4.z, a4.w};
#pragma unroll
            for (int i = 0; i < 4; i++) {
                uint64_t as = splat2(aa[i]);
                accP[i][0] = fma2(as, b2.x, accP[i][0]);
                accP[i][1] = fma2(as, b2.y, accP[i][1]);
            }
        }

        if (kn < KIN) {
            const int nxt = cur ^ 1;
            As[nxt][lk4 + 0][lm] = av2.x;
            As[nxt][lk4 + 1][lm] = av2.y;
            As[nxt][lk4 + 2][lm] = av2.z;
            As[nxt][lk4 + 3][lm] = av2.w;
            *(float4*)&Bs[nxt][lk][ln] = bv2;
            __syncthreads();
            cur = nxt;
        }
    }

    const float4 bias4 = *(const float4*)&catBias[n0 + tx * 4];
#pragma unroll
    for (int i = 0; i < 4; i++) {
        float s0, s1, s2, s3;
        unpack2(accP[i][0], s0, s1);
        unpack2(accP[i][1], s2, s3);
        float4 v;
        v.x = fast_tanh(s0 + bias4.x);
        v.y = fast_tanh(s1 + bias4.y);
        v.z = fast_tanh(s2 + bias4.z);
        v.w = fast_tanh(s3 + bias4.w);
        *(float4*)&out[(size_t)(m0 + ty * 4 + i) * HH + wcol + tx * 4] = v;
    }
}

// ---------------------------------------------------------------------------
// Kernel 2: E = ex2( c * (a @ W + bias) ), written DEINTERLEAVED by quad
// member (h mod 4): col 4q+k -> g_E?(k+1)[row*NQUAD + q].
// Each thread's 4 columns (col0 + tx*4 .. +3) form exactly one quad.
// Grid (8,16) = 128 blocks; n0<256 -> head (Ep), else mod (Eq, bias).
// ---------------------------------------------------------------------------
__global__ __launch_bounds__(256)
void gemm2_exp(const float* __restrict__ h2L, const float* __restrict__ h2B) {
    __shared__ __align__(16) float As[2][16][68];
    __shared__ __align__(16) float Bs[2][16][68];

    const int tid = threadIdx.x;
    const int n0 = blockIdx.x * 64;        // combined N (0..511)
    const int m0 = blockIdx.y * 64;

    const bool isP = (n0 < 256);
    const float* __restrict__ Asrc = isP ? g_ah : g_am;
    const int   wrow = isP ? 0 : 512;
    const int   col0 = isP ? n0 : (n0 - 256);
    float* __restrict__ out1 = isP ? g_Ep1 : g_Eq1;
    float* __restrict__ out2 = isP ? g_Ep2 : g_Eq2;
    float* __restrict__ out3 = isP ? g_Ep3 : g_Eq3;
    float* __restrict__ out4 = isP ? g_Ep4 : g_Eq4;

    const int tx = tid & 15;
    const int ty = tid >> 4;
    const int lm  = tid >> 2;
    const int lk4 = (tid & 3) * 4;
    const int lk  = tid >> 4;
    const int ln  = (tid & 15) * 4;

    float4 av = *(const float4*)(Asrc + (size_t)(m0 + lm) * HH + lk4);
    float4 bv = *(const float4*)(h2L + (size_t)(wrow + lk) * H2D + col0 + ln);
    As[0][lk4 + 0][lm] = av.x;
    As[0][lk4 + 1][lm] = av.y;
    As[0][lk4 + 2][lm] = av.z;
    As[0][lk4 + 3][lm] = av.w;
    *(float4*)&Bs[0][lk][ln] = bv;
    __syncthreads();

    uint64_t accP[4][2] = {};
    int cur = 0;

    for (int k0 = 0; k0 < HH; k0 += 16) {
        float4 av2, bv2;
        const int kn = k0 + 16;
        if (kn < HH) {
            av2 = *(const float4*)(Asrc + (size_t)(m0 + lm) * HH + kn + lk4);
            bv2 = *(const float4*)(h2L + (size_t)(wrow + kn + lk) * H2D + col0 + ln);
        }

#pragma unroll
        for (int kk = 0; kk < 16; kk++) {
            float4 a4 = *(const float4*)&As[cur][kk][ty * 4];
            ulonglong2 b2 = *(const ulonglong2*)&Bs[cur][kk][tx * 4];
            float aa[4] = {a4.x, a4.y, a4.z, a4.w};
#pragma unroll
            for (int i = 0; i < 4; i++) {
                uint64_t as = splat2(aa[i]);
                accP[i][0] = fma2(as, b2.x, accP[i][0]);
                accP[i][1] = fma2(as, b2.y, accP[i][1]);
            }
        }

        if (kn < HH) {
            const int nxt = cur ^ 1;
            As[nxt][lk4 + 0][lm] = av2.x;
            As[nxt][lk4 + 1][lm] = av2.y;
            As[nxt][lk4 + 2][lm] = av2.z;
            As[nxt][lk4 + 3][lm] = av2.w;
            *(float4*)&Bs[nxt][lk][ln] = bv2;
            __syncthreads();
            cur = nxt;
        }
    }

    const int q = (col0 + tx * 4) >> 2;    // this thread's quad index (0..63)
#pragma unroll
    for (int i = 0; i < 4; i++) {
        float s0, s1, s2, s3;
        unpack2(accP[i][0], s0, s1);
        unpack2(accP[i][1], s2, s3);
        float b0 = isP ? 0.0f : h2B[col0 + tx * 4 + 0];
        float b1 = isP ? 0.0f : h2B[col0 + tx * 4 + 1];
        float b2 = isP ? 0.0f : h2B[col0 + tx * 4 + 2];
        float b3 = isP ? 0.0f : h2B[col0 + tx * 4 + 3];
        const size_t row = (size_t)(m0 + ty * 4 + i) * NQUAD;
        out1[row + q] = fast_ex2((s0 + b0) * SCALE_2LOG2E);
        out2[row + q] = fast_ex2((s1 + b1) * SCALE_2LOG2E);
        out3[row + q] = fast_ex2((s2 + b2) * SCALE_2LOG2E);
        out4[row + q] = fast_ex2((s3 + b3) * SCALE_2LOG2E);
    }
}

// ---------------------------------------------------------------------------
// Kernel 3: g_C = sum(outLayer) + outBias; g_w1..4 = -2*w split by h mod 4
// ---------------------------------------------------------------------------
__global__ void sumw_kernel(const float* __restrict__ outL,
                            const float* __restrict__ outB) {
    __shared__ float s[256];
    const int t = threadIdx.x;
    s[t] = outL[t];
    if (t < NQUAD) {
        g_w1[t] = -2.0f * outL[4 * t + 0];
        g_w2[t] = -2.0f * outL[4 * t + 1];
        g_w3[t] = -2.0f * outL[4 * t + 2];
        g_w4[t] = -2.0f * outL[4 * t + 3];
    }
    __syncthreads();
    for (int o = 128; o > 0; o >>= 1) {
        if (t < o) s[t] += s[t + o];
        __syncthreads();
    }
    if (t == 0) g_C = s[0] + outB[0];
}

// ---------------------------------------------------------------------------
// Kernel 4: pairwise scores, quad-merged (0.25 MUFU / element):
//   per quad: u_k = 1 + Ep_k*Eq_k (k=1..4)
//   v12=u1*u2, v34=u3*u4, s12=w1*u2+w2*u1, s34=w3*u4+w4*u3
//   contribution = (s12*v34 + s34*v12) / (v12*v34)      [single rcp]
// Packed f32x2 over two adjacent quads: 14 fma2 + 2 rcp per 8 h-elements.
// 64x64 tile / block, 256 threads, 4x4 micro (rows ty+16r, cols tx+16c).
// Quads in 4 chunks of 16. Rows padded to 20 floats (80 B, 16B-aligned).
// ---------------------------------------------------------------------------
__global__ __launch_bounds__(256, 2)
void pairwise_kernel(float* __restrict__ out) {
    __shared__ __align__(16) float E1p[64][20];
    __shared__ __align__(16) float E2p[64][20];
    __shared__ __align__(16) float E3p[64][20];
    __shared__ __align__(16) float E4p[64][20];
    __shared__ __align__(16) float E1q[64][20];
    __shared__ __align__(16) float E2q[64][20];
    __shared__ __align__(16) float E3q[64][20];
    __shared__ __align__(16) float E4q[64][20];
    __shared__ __align__(16) float ws1[NQUAD];
    __shared__ __align__(16) float ws2[NQUAD];
    __shared__ __align__(16) float ws3[NQUAD];
    __shared__ __align__(16) float ws4[NQUAD];

    const int tid = threadIdx.x;
    if (tid < NQUAD) {
        ws1[tid] = g_w1[tid];
        ws2[tid] = g_w2[tid];
        ws3[tid] = g_w3[tid];
        ws4[tid] = g_w4[tid];
    }

    const int j0 = (blockIdx.x & 15) * 64;
    const int i0 = (blockIdx.x >> 4) * 64;

    const int tx = tid & 15;
    const int ty = tid >> 4;

    // staging indices: one float4 per thread per array per chunk
    const int srow = tid >> 2;             // 0..63
    const int scol = (tid & 3) * 4;        // 0,4,8,12

    uint64_t accP[4][4] = {};   // f32x2: lo = quad 2s, hi = quad 2s+1

    for (int ch = 0; ch < 4; ch++) {
        __syncthreads();   // ws visible (ch=0) / prior chunk reads done
        {
            const size_t gi = (size_t)(i0 + srow) * NQUAD + ch * 16 + scol;
            const size_t gj = (size_t)(j0 + srow) * NQUAD + ch * 16 + scol;
            *(float4*)&E1p[srow][scol] = *(const float4*)&g_Ep1[gi];
            *(float4*)&E2p[srow][scol] = *(const float4*)&g_Ep2[gi];
            *(float4*)&E3p[srow][scol] = *(const float4*)&g_Ep3[gi];
            *(float4*)&E4p[srow][scol] = *(const float4*)&g_Ep4[gi];
            *(float4*)&E1q[srow][scol] = *(const float4*)&g_Eq1[gj];
            *(float4*)&E2q[srow][scol] = *(const float4*)&g_Eq2[gj];
            *(float4*)&E3q[srow][scol] = *(const float4*)&g_Eq3[gj];
            *(float4*)&E4q[srow][scol] = *(const float4*)&g_Eq4[gj];
        }
        __syncthreads();

#pragma unroll
        for (int s = 0; s < 8; s++) {      // 8 packed steps x 2 quads
            uint64_t A1[4], A2[4], A3[4], A4[4];
#pragma unroll
            for (int r = 0; r < 4; r++) {
                A1[r] = *(const uint64_t*)&E1p[ty + 16 * r][2 * s];
                A2[r] = *(const uint64_t*)&E2p[ty + 16 * r][2 * s];
                A3[r] = *(const uint64_t*)&E3p[ty + 16 * r][2 * s];
                A4[r] = *(const uint64_t*)&E4p[ty + 16 * r][2 * s];
            }
            const uint64_t W1 = *(const uint64_t*)&ws1[ch * 16 + 2 * s];
            const uint64_t W2 = *(const uint64_t*)&ws2[ch * 16 + 2 * s];
            const uint64_t W3 = *(const uint64_t*)&ws3[ch * 16 + 2 * s];
            const uint64_t W4 = *(const uint64_t*)&ws4[ch * 16 + 2 * s];

#pragma unroll
            for (int c = 0; c < 4; c++) {
                const uint64_t B1 = *(const uint64_t*)&E1q[tx + 16 * c][2 * s];
                const uint64_t B2 = *(const uint64_t*)&E2q[tx + 16 * c][2 * s];
                const uint64_t B3 = *(const uint64_t*)&E3q[tx + 16 * c][2 * s];
                const uint64_t B4 = *(const uint64_t*)&E4q[tx + 16 * c][2 * s];
#pragma unroll
                for (int r = 0; r < 4; r++) {
                    uint64_t u1 = fma2(A1[r], B1, (uint64_t)ONE2);
                    uint64_t u2 = fma2(A2[r], B2, (uint64_t)ONE2);
                    uint64_t u3 = fma2(A3[r], B3, (uint64_t)ONE2);
                    uint64_t u4 = fma2(A4[r], B4, (uint64_t)ONE2);
                    uint64_t v12 = mul2(u1, u2);
                    uint64_t v34 = mul2(u3, u4);
                    uint64_t den = mul2(v12, v34);
                    uint64_t s12 = fma2(W1, u2, mul2(W2, u1));
                    uint64_t s34 = fma2(W3, u4, mul2(W4, u3));
                    uint64_t num = fma2(s12, v34, mul2(s34, v12));
                    float d0, d1;
                    unpack2(den, d0, d1);
                    uint64_t rr = pack2(rcpf(d0), rcpf(d1));
                    accP[r][c] = fma2(num, rr, accP[r][c]);
                }
            }
        }
    }

    const float C = g_C;
#pragma unroll
    for (int r = 0; r < 4; r++) {
#pragma unroll
        for (int c = 0; c < 4; c++) {
            float lo, hi;
            unpack2(accP[r][c], lo, hi);
            out[(size_t)(i0 + ty + 16 * r) * NTOK + (j0 + tx + 16 * c)]
                = C + (lo + hi);
        }
    }
}

// ---------------------------------------------------------------------------
extern "C" void kernel_launch(void* const* d_in, const int* in_sizes, int n_in,
                              void* d_out, int out_size) {
    const float* l0   = (const float*)d_in[0];   // lstms0 [1024,256]
    const float* l1   = (const float*)d_in[1];   // lstms1 [1024,256]
    const float* Wfoh = (const float*)d_in[2];   // [512,512]
    const float* Wfom = (const float*)d_in[3];   // [512,512]
    const float* catB = (const float*)d_in[4];   // [1,1024]
    const float* h2L  = (const float*)d_in[5];   // [1024,256]
    const float* h2B  = (const float*)d_in[6];   // [1,256]
    const float* outL = (const float*)d_in[7];   // [256,1]
    const float* outB = (const float*)d_in[8];   // [1,1]
    float* out = (float*)d_out;                  // [1024,1024]

    gemm1_tanh<<<dim3(16, 16), 256>>>(l0, l1, Wfoh, Wfom, catB);
    gemm2_exp<<<dim3(8, 16), 256>>>(h2L, h2B);
    sumw_kernel<<<1, 256>>>(outL, outB);
    pairwise_kernel<<<256, 256>>>(out);
}

// round 17
// speedup vs baseline: 1.0542x; 1.0542x over previous
#include <cuda_runtime.h>
#include <cstdint>

// Shapes (fixed): n=1024 tokens, 2L=512, H=512, H2=256.
#define NTOK 1024
#define KIN  512
#define HH   512
#define H2D  256
#define NQUAD 64                          // H2/4 quad-merged terms
#define SCALE_2LOG2E 2.885390081777927f   // 2*log2(e)
#define ONE2 0x3F8000003F800000ULL        // (1.0f, 1.0f) packed

// Scratch (device globals; no allocations allowed)
__device__ float g_ah[NTOK * HH];
__device__ float g_am[NTOK * HH];
__device__ float g_Ep1[NTOK * NQUAD];  // head side, quad member 0 (h = 4q)
__device__ float g_Ep2[NTOK * NQUAD];  // member 1 (h = 4q+1)
__device__ float g_Ep3[NTOK * NQUAD];  // member 2
__device__ float g_Ep4[NTOK * NQUAD];  // member 3
__device__ float g_Eq1[NTOK * NQUAD];  // mod side (bias folded), member 0
__device__ float g_Eq2[NTOK * NQUAD];
__device__ float g_Eq3[NTOK * NQUAD];
__device__ float g_Eq4[NTOK * NQUAD];
__device__ float g_w1[NQUAD];          // -2*w[4q+0]
__device__ float g_w2[NQUAD];          // -2*w[4q+1]
__device__ float g_w3[NQUAD];          // -2*w[4q+2]
__device__ float g_w4[NQUAD];          // -2*w[4q+3]
__device__ float g_C;                  // sum(w) + outBias

// ---------------- packed f32x2 helpers (sm_103a FFMA2 path) ----------------
__device__ __forceinline__ uint64_t fma2(uint64_t a, uint64_t b, uint64_t c) {
    uint64_t d;
    asm("fma.rn.f32x2 %0, %1, %2, %3;" : "=l"(d) : "l"(a), "l"(b), "l"(c));
    return d;
}
__device__ __forceinline__ uint64_t mul2(uint64_t a, uint64_t b) {
    uint64_t d;
    asm("mul.rn.f32x2 %0, %1, %2;" : "=l"(d) : "l"(a), "l"(b));
    return d;
}
__device__ __forceinline__ uint64_t pack2(float lo, float hi) {
    uint64_t d;
    asm("mov.b64 %0, {%1, %2};" : "=l"(d) : "f"(lo), "f"(hi));
    return d;
}
__device__ __forceinline__ void unpack2(uint64_t p, float& lo, float& hi) {
    asm("mov.b64 {%0, %1}, %2;" : "=f"(lo), "=f"(hi) : "l"(p));
}
__device__ __forceinline__ uint64_t splat2(float v) {
    uint64_t d;
    asm("mov.b64 %0, {%1, %1};" : "=l"(d) : "f"(v));
    return d;
}
__device__ __forceinline__ float rcpf(float x) {
    float r;
    asm("rcp.approx.f32 %0, %1;" : "=f"(r) : "f"(x));
    return r;
}
__device__ __forceinline__ float fast_tanh(float x) {   // 1 - 2/(exp(2x)+1)
    float e;
    asm("ex2.approx.f32 %0, %1;" : "=f"(e) : "f"(x * SCALE_2LOG2E));
    return 1.0f - 2.0f * rcpf(e + 1.0f);
}
__device__ __forceinline__ float fast_ex2(float x) {
    float e;
    asm("ex2.approx.f32 %0, %1;" : "=f"(e) : "f"(x));
    return e;
}

// ---------------------------------------------------------------------------
// Kernel 1: [ah | am] = tanh( x @ [W_foh | W_fom] + catBias )
// 64x64 tile, BK=16, 256 threads, 4x4 micro (acc packed f32x2 along j),
// double-buffered smem. Grid (16,16) = 256 blocks.
// ---------------------------------------------------------------------------
__global__ __launch_bounds__(256)
void gemm1_tanh(const float* __restrict__ l0, const float* __restrict__ l1,
                const float* __restrict__ Wfoh, const float* __restrict__ Wfom,
                const float* __restrict__ catBias) {
    __shared__ __align__(16) float As[2][16][68];   // As[buf][k][m]
    __shared__ __align__(16) float Bs[2][16][68];   // Bs[buf][k][n]

    const int tid = threadIdx.x;
    const int n0 = blockIdx.x * 64;        // combined N (0..1023)
    const int m0 = blockIdx.y * 64;

    const bool head = (n0 < 512);
    const float* __restrict__ W = head ? Wfoh : Wfom;
    const int   wcol = head ? n0 : (n0 - 512);
    float* __restrict__ out = head ? g_ah : g_am;

    const int tx = tid & 15;
    const int ty = tid >> 4;
    const int lm  = tid >> 2;              // 0..63 (A rows)
    const int lk4 = (tid & 3) * 4;         // 0,4,8,12
    const int lk  = tid >> 4;              // 0..15 (B k)
    const int ln  = (tid & 15) * 4;        // 0..60 (B n)

    float4 av = *(const float4*)(l0 + (size_t)(m0 + lm) * 256 + lk4);
    float4 bv = *(const float4*)(W + (size_t)lk * HH + wcol + ln);
    As[0][lk4 + 0][lm] = av.x;
    As[0][lk4 + 1][lm] = av.y;
    As[0][lk4 + 2][lm] = av.z;
    As[0][lk4 + 3][lm] = av.w;
    *(float4*)&Bs[0][lk][ln] = bv;
    __syncthreads();

    uint64_t accP[4][2] = {};              // [i][j-pair], f32x2
    int cur = 0;

    for (int k0 = 0; k0 < KIN; k0 += 16) {
        float4 av2, bv2;
        const int kn = k0 + 16;
        if (kn < KIN) {
            const float* __restrict__ xsrc =
                (kn < 256) ? (l0 + (size_t)(m0 + lm) * 256 + (kn + lk4))
                           : (l1 + (size_t)(m0 + lm) * 256 + (kn - 256 + lk4));
            av2 = *(const float4*)xsrc;
            bv2 = *(const float4*)(W + (size_t)(kn + lk) * HH + wcol + ln);
        }

#pragma unroll
        for (int kk = 0; kk < 16; kk++) {
            float4 a4 = *(const float4*)&As[cur][kk][ty * 4];
            ulonglong2 b2 = *(const ulonglong2*)&Bs[cur][kk][tx * 4];
            float aa[4] = {a4.x, a4.y, a4.z, a4.w};
#pragma unroll
            for (int i = 0; i < 4; i++) {
                uint64_t as = splat2(aa[i]);
                accP[i][0] = fma2(as, b2.x, accP[i][0]);
                accP[i][1] = fma2(as, b2.y, accP[i][1]);
            }
        }

        if (kn < KIN) {
            const int nxt = cur ^ 1;
            As[nxt][lk4 + 0][lm] = av2.x;
            As[nxt][lk4 + 1][lm] = av2.y;
            As[nxt][lk4 + 2][lm] = av2.z;
            As[nxt][lk4 + 3][lm] = av2.w;
            *(float4*)&Bs[nxt][lk][ln] = bv2;
            __syncthreads();
            cur = nxt;
        }
    }

    const float4 bias4 = *(const float4*)&catBias[n0 + tx * 4];
#pragma unroll
    for (int i = 0; i < 4; i++) {
        float s0, s1, s2, s3;
        unpack2(accP[i][0], s0, s1);
        unpack2(accP[i][1], s2, s3);
        float4 v;
        v.x = fast_tanh(s0 + bias4.x);
        v.y = fast_tanh(s1 + bias4.y);
        v.z = fast_tanh(s2 + bias4.z);
        v.w = fast_tanh(s3 + bias4.w);
        *(float4*)&out[(size_t)(m0 + ty * 4 + i) * HH + wcol + tx * 4] = v;
    }
}

// ---------------------------------------------------------------------------
// Kernel 2: E = ex2( c * (a @ W + bias) ), written DEINTERLEAVED by quad
// member (h mod 4): col 4q+k -> g_E?(k+1)[row*NQUAD + q].
// Each thread's 4 columns (col0 + tx*4 .. +3) form exactly one quad.
// Grid (8,16) = 128 blocks; n0<256 -> head (Ep), else mod (Eq, bias).
// ---------------------------------------------------------------------------
__global__ __launch_bounds__(256)
void gemm2_exp(const float* __restrict__ h2L, const float* __restrict__ h2B) {
    __shared__ __align__(16) float As[2][16][68];
    __shared__ __align__(16) float Bs[2][16][68];

    const int tid = threadIdx.x;
    const int n0 = blockIdx.x * 64;        // combined N (0..511)
    const int m0 = blockIdx.y * 64;

    const bool isP = (n0 < 256);
    const float* __restrict__ Asrc = isP ? g_ah : g_am;
    const int   wrow = isP ? 0 : 512;
    const int   col0 = isP ? n0 : (n0 - 256);
    float* __restrict__ out1 = isP ? g_Ep1 : g_Eq1;
    float* __restrict__ out2 = isP ? g_Ep2 : g_Eq2;
    float* __restrict__ out3 = isP ? g_Ep3 : g_Eq3;
    float* __restrict__ out4 = isP ? g_Ep4 : g_Eq4;

    const int tx = tid & 15;
    const int ty = tid >> 4;
    const int lm  = tid >> 2;
    const int lk4 = (tid & 3) * 4;
    const int lk  = tid >> 4;
    const int ln  = (tid & 15) * 4;

    float4 av = *(const float4*)(Asrc + (size_t)(m0 + lm) * HH + lk4);
    float4 bv = *(const float4*)(h2L + (size_t)(wrow + lk) * H2D + col0 + ln);
    As[0][lk4 + 0][lm] = av.x;
    As[0][lk4 + 1][lm] = av.y;
    As[0][lk4 + 2][lm] = av.z;
    As[0][lk4 + 3][lm] = av.w;
    *(float4*)&Bs[0][lk][ln] = bv;
    __syncthreads();

    uint64_t accP[4][2] = {};
    int cur = 0;

    for (int k0 = 0; k0 < HH; k0 += 16) {
        float4 av2, bv2;
        const int kn = k0 + 16;
        if (kn < HH) {
            av2 = *(const float4*)(Asrc + (size_t)(m0 + lm) * HH + kn + lk4);
            bv2 = *(const float4*)(h2L + (size_t)(wrow + kn + lk) * H2D + col0 + ln);
        }

#pragma unroll
        for (int kk = 0; kk < 16; kk++) {
            float4 a4 = *(const float4*)&As[cur][kk][ty * 4];
            ulonglong2 b2 = *(const ulonglong2*)&Bs[cur][kk][tx * 4];
            float aa[4] = {a4.x, a4.y, a4.z, a4.w};
#pragma unroll
            for (int i = 0; i < 4; i++) {
                uint64_t as = splat2(aa[i]);
                accP[i][0] = fma2(as, b2.x, accP[i][0]);
                accP[i][1] = fma2(as, b2.y, accP[i][1]);
            }
        }

        if (kn < HH) {
            const int nxt = cur ^ 1;
            As[nxt][lk4 + 0][lm] = av2.x;
            As[nxt][lk4 + 1][lm] = av2.y;
            As[nxt][lk4 + 2][lm] = av2.z;
            As[nxt][lk4 + 3][lm] = av2.w;
            *(float4*)&Bs[nxt][lk][ln] = bv2;
            __syncthreads();
            cur = nxt;
        }
    }

    const int q = (col0 + tx * 4) >> 2;    // this thread's quad index (0..63)
#pragma unroll
    for (int i = 0; i < 4; i++) {
        float s0, s1, s2, s3;
        unpack2(accP[i][0], s0, s1);
        unpack2(accP[i][1], s2, s3);
        float b0 = isP ? 0.0f : h2B[col0 + tx * 4 + 0];
        float b1 = isP ? 0.0f : h2B[col0 + tx * 4 + 1];
        float b2 = isP ? 0.0f : h2B[col0 + tx * 4 + 2];
        float b3 = isP ? 0.0f : h2B[col0 + tx * 4 + 3];
        const size_t row = (size_t)(m0 + ty * 4 + i) * NQUAD;
        out1[row + q] = fast_ex2((s0 + b0) * SCALE_2LOG2E);
        out2[row + q] = fast_ex2((s1 + b1) * SCALE_2LOG2E);
        out3[row + q] = fast_ex2((s2 + b2) * SCALE_2LOG2E);
        out4[row + q] = fast_ex2((s3 + b3) * SCALE_2LOG2E);
    }
}

// ---------------------------------------------------------------------------
// Kernel 3: g_C = sum(outLayer) + outBias; g_w1..4 = -2*w split by h mod 4
// ---------------------------------------------------------------------------
__global__ void sumw_kernel(const float* __restrict__ outL,
                            const float* __restrict__ outB) {
    __shared__ float s[256];
    const int t = threadIdx.x;
    s[t] = outL[t];
    if (t < NQUAD) {
        g_w1[t] = -2.0f * outL[4 * t + 0];
        g_w2[t] = -2.0f * outL[4 * t + 1];
        g_w3[t] = -2.0f * outL[4 * t + 2];
        g_w4[t] = -2.0f * outL[4 * t + 3];
    }
    __syncthreads();
    for (int o = 128; o > 0; o >>= 1) {
        if (t < o) s[t] += s[t + o];
        __syncthreads();
    }
    if (t == 0) g_C = s[0] + outB[0];
}

// ---------------------------------------------------------------------------
// Kernel 4: pairwise scores, quad-merged (0.25 MUFU / element):
//   per quad: u_k = 1 + Ep_k*Eq_k (k=1..4)
//   v12=u1*u2, v34=u3*u4, s12=w1*u2+w2*u1, s34=w3*u4+w4*u3
//   contribution = (s12*v34 + s34*v12) / (v12*v34)      [single rcp]
// Register blocking REORDERED vs R16 to kill spills: B (cols) + W cached
// across the row loop (32+8 regs), A loaded per row (8 short-lived regs).
// Peak live ~100 regs < 128 cap. LDS.64 per s-step: 16 B + 16 A = 32.
// 64x64 tile / block, 256 threads, 4x4 micro. Quads in 4 chunks of 16.
// ---------------------------------------------------------------------------
__global__ __launch_bounds__(256, 2)
void pairwise_kernel(float* __restrict__ out) {
    __shared__ __align__(16) float E1p[64][20];
    __shared__ __align__(16) float E2p[64][20];
    __shared__ __align__(16) float E3p[64][20];
    __shared__ __align__(16) float E4p[64][20];
    __shared__ __align__(16) float E1q[64][20];
    __shared__ __align__(16) float E2q[64][20];
    __shared__ __align__(16) float E3q[64][20];
    __shared__ __align__(16) float E4q[64][20];
    __shared__ __align__(16) float ws1[NQUAD];
    __shared__ __align__(16) float ws2[NQUAD];
    __shared__ __align__(16) float ws3[NQUAD];
    __shared__ __align__(16) float ws4[NQUAD];

    const int tid = threadIdx.x;
    if (tid < NQUAD) {
        ws1[tid] = g_w1[tid];
        ws2[tid] = g_w2[tid];
        ws3[tid] = g_w3[tid];
        ws4[tid] = g_w4[tid];
    }

    const int j0 = (blockIdx.x & 15) * 64;
    const int i0 = (blockIdx.x >> 4) * 64;

    const int tx = tid & 15;
    const int ty = tid >> 4;

    // staging indices: one float4 per thread per array per chunk
    const int srow = tid >> 2;             // 0..63
    const int scol = (tid & 3) * 4;        // 0,4,8,12

    uint64_t accP[4][4] = {};   // f32x2: lo = quad 2s, hi = quad 2s+1

    for (int ch = 0; ch < 4; ch++) {
        __syncthreads();   // ws visible (ch=0) / prior chunk reads done
        {
            const size_t gi = (size_t)(i0 + srow) * NQUAD + ch * 16 + scol;
            const size_t gj = (size_t)(j0 + srow) * NQUAD + ch * 16 + scol;
            *(float4*)&E1p[srow][scol] = *(const float4*)&g_Ep1[gi];
            *(float4*)&E2p[srow][scol] = *(const float4*)&g_Ep2[gi];
            *(float4*)&E3p[srow][scol] = *(const float4*)&g_Ep3[gi];
            *(float4*)&E4p[srow][scol] = *(const float4*)&g_Ep4[gi];
            *(float4*)&E1q[srow][scol] = *(const float4*)&g_Eq1[gj];
            *(float4*)&E2q[srow][scol] = *(const float4*)&g_Eq2[gj];
            *(float4*)&E3q[srow][scol] = *(const float4*)&g_Eq3[gj];
            *(float4*)&E4q[srow][scol] = *(const float4*)&g_Eq4[gj];
        }
        __syncthreads();

#pragma unroll 2
        for (int s = 0; s < 8; s++) {      // 8 packed steps x 2 quads
            // Cache B (columns) and W across the row loop.
            uint64_t B1[4], B2[4], B3[4], B4[4];
#pragma unroll
            for (int c = 0; c < 4; c++) {
                B1[c] = *(const uint64_t*)&E1q[tx + 16 * c][2 * s];
                B2[c] = *(const uint64_t*)&E2q[tx + 16 * c][2 * s];
                B3[c] = *(const uint64_t*)&E3q[tx + 16 * c][2 * s];
                B4[c] = *(const uint64_t*)&E4q[tx + 16 * c][2 * s];
            }
            const uint64_t W1 = *(const uint64_t*)&ws1[ch * 16 + 2 * s];
            const uint64_t W2 = *(const uint64_t*)&ws2[ch * 16 + 2 * s];
            const uint64_t W3 = *(const uint64_t*)&ws3[ch * 16 + 2 * s];
            const uint64_t W4 = *(const uint64_t*)&ws4[ch * 16 + 2 * s];

#pragma unroll
            for (int r = 0; r < 4; r++) {
                // A loaded per row: short-lived (8 regs), freed before next r.
                const uint64_t A1 = *(const uint64_t*)&E1p[ty + 16 * r][2 * s];
                const uint64_t A2 = *(const uint64_t*)&E2p[ty + 16 * r][2 * s];
                const uint64_t A3 = *(const uint64_t*)&E3p[ty + 16 * r][2 * s];
                const uint64_t A4 = *(const uint64_t*)&E4p[ty + 16 * r][2 * s];
#pragma unroll
                for (int c = 0; c < 4; c++) {
                    uint64_t u1 = fma2(A1, B1[c], (uint64_t)ONE2);
                    uint64_t u2 = fma2(A2, B2[c], (uint64_t)ONE2);
                    uint64_t u3 = fma2(A3, B3[c], (uint64_t)ONE2);
                    uint64_t u4 = fma2(A4, B4[c], (uint64_t)ONE2);
                    uint64_t v12 = mul2(u1, u2);
                    uint64_t v34 = mul2(u3, u4);
                    uint64_t den = mul2(v12, v34);
                    uint64_t s12 = fma2(W1, u2, mul2(W2, u1));
                    uint64_t s34 = fma2(W3, u4, mul2(W4, u3));
                    uint64_t num = fma2(s12, v34, mul2(s34, v12));
                    float d0, d1;
                    unpack2(den, d0, d1);
                    uint64_t rr = pack2(rcpf(d0), rcpf(d1));
                    accP[r][c] = fma2(num, rr, accP[r][c]);
                }
            }
        }
    }

    const float C = g_C;
#pragma unroll
    for (int r = 0; r < 4; r++) {
#pragma unroll
        for (int c = 0; c < 4; c++) {
            float lo, hi;
            unpack2(accP[r][c], lo, hi);
            out[(size_t)(i0 + ty + 16 * r) * NTOK + (j0 + tx + 16 * c)]
                = C + (lo + hi);
        }
    }
}

// ---------------------------------------------------------------------------
extern "C" void kernel_launch(void* const* d_in, const int* in_sizes, int n_in,
                              void* d_out, int out_size) {
    const float* l0   = (const float*)d_in[0];   // lstms0 [1024,256]
    const float* l1   = (const float*)d_in[1];   // lstms1 [1024,256]
    const float* Wfoh = (const float*)d_in[2];   // [512,512]
    const float* Wfom = (const float*)d_in[3];   // [512,512]
    const float* catB = (const float*)d_in[4];   // [1,1024]
    const float* h2L  = (const float*)d_in[5];   // [1024,256]
    const float* h2B  = (const float*)d_in[6];   // [1,256]
    const float* outL = (const float*)d_in[7];   // [256,1]
    const float* outB = (const float*)d_in[8];   // [1,1]
    float* out = (float*)d_out;                  // [1024,1024]

    gemm1_tanh<<<dim3(16, 16), 256>>>(l0, l1, Wfoh, Wfom, catB);
    gemm2_exp<<<dim3(8, 16), 256>>>(h2L, h2B);
    sumw_kernel<<<1, 256>>>(outL, outB);
    pairwise_kernel<<<256, 256>>>(out);
}